// round 6
// baseline (speedup 1.0000x reference)
#include <cuda_runtime.h>
#include <math.h>

#define TT 2048
#define DD 1024
#define NH 16
#define NKV 4
#define HD 64
#define NE 8
#define FF 2048
#define VV 32000
#define WIN 1024
#define NGLB 32

// ---------------- scratch (device globals; allocation-free) ----------------
__device__ float g_x[TT * DD];
__device__ float g_h[TT * DD];
__device__ float g_q[TT * NH * HD];
__device__ float g_k[TT * NKV * HD];
__device__ float g_v[TT * NKV * HD];
__device__ float g_attn[TT * DD];
__device__ float g_cos[TT * 32];
__device__ float g_sin[TT * 32];
__device__ float g_up[NE * TT * FF];     // up-proj, dense per expert
__device__ float g_gate[NE * TT * FF];   // gate-proj, then silu(gate)*up in place
__device__ float g_y[NE * TT * DD];      // down-proj outputs, dense
__device__ float g_w[TT * NE];           // dense combine weights (0 except top-2)
__device__ int   g_counts[NE];
__device__ float g_probsum[NE];
__device__ float g_aux;

// ---------------- small kernels ----------------
__global__ void embed_kernel(const int* __restrict__ tok, const float* __restrict__ emb,
                             float* __restrict__ x) {
    int idx = blockIdx.x * 256 + threadIdx.x;   // TT*DD total
    int t = idx >> 10, d = idx & 1023;
    x[idx] = emb[(size_t)tok[t] * DD + d];
}

__global__ void rope_table_kernel() {
    int idx = blockIdx.x * 256 + threadIdx.x;   // TT*32 total
    int t = idx >> 5, i = idx & 31;
    float inv = 1.0f / powf(500000.0f, (float)(2 * i) * (1.0f / 64.0f));
    float ang = (float)t * inv;
    g_cos[idx] = cosf(ang);
    g_sin[idx] = sinf(ang);
}

__global__ void rmsnorm_kernel(const float* __restrict__ x, const float* __restrict__ w,
                               float* __restrict__ o) {
    int t = blockIdx.x, tid = threadIdx.x;
    const float* xr = x + (size_t)t * DD;
    float ss = 0.f;
    for (int d = tid; d < DD; d += 256) { float v = xr[d]; ss += v * v; }
    #pragma unroll
    for (int off = 16; off; off >>= 1) ss += __shfl_down_sync(0xffffffffu, ss, off);
    __shared__ float sred[8];
    __shared__ float sinv;
    if ((tid & 31) == 0) sred[tid >> 5] = ss;
    __syncthreads();
    if (tid == 0) {
        float tot = 0.f;
        #pragma unroll
        for (int i = 0; i < 8; i++) tot += sred[i];
        sinv = rsqrtf(tot * (1.0f / DD) + 1.1920929e-07f);
    }
    __syncthreads();
    float inv = sinv;
    for (int d = tid; d < DD; d += 256) o[(size_t)t * DD + d] = xr[d] * inv * w[d];
}

// ---------------- naive exact attention: one block per (query, head) ----------------
// RoPE applied inline to raw q/k. Full-row two-pass softmax, exact reference mask.
__global__ void __launch_bounds__(256) attn_naive_kernel(const float* __restrict__ q,
                                                         const float* __restrict__ k,
                                                         const float* __restrict__ v,
                                                         float* __restrict__ out) {
    int i = blockIdx.x, h = blockIdx.y, kvh = h >> 2;
    int tid = threadIdx.x;
    __shared__ float qsh[64];
    __shared__ float sc[TT];
    __shared__ float red[8];
    __shared__ float accs[4][64];

    if (tid < 32) {
        float c = g_cos[i * 32 + tid], s = g_sin[i * 32 + tid];
        float a = q[(size_t)i * (NH * HD) + h * HD + tid];
        float b = q[(size_t)i * (NH * HD) + h * HD + tid + 32];
        qsh[tid]      = (a * c - b * s) * 0.125f;
        qsh[tid + 32] = (b * c + a * s) * 0.125f;
    }
    __syncthreads();

    // pass 1: scores (with inline k-rope) + max
    float lmax = -1e30f;
    for (int j = tid; j < TT; j += 256) {
        bool ok = (j <= i) && ((i - j) < WIN || j < NGLB);
        float s = -1e30f;
        if (ok) {
            const float* kr = k + (size_t)j * (NKV * HD) + kvh * HD;
            const float* cj = g_cos + j * 32;
            const float* sj = g_sin + j * 32;
            s = 0.f;
            #pragma unroll
            for (int d = 0; d < 32; d++) {
                float c = cj[d], sn = sj[d];
                float ka = kr[d], kb = kr[d + 32];
                float k0 = ka * c - kb * sn;
                float k1 = kb * c + ka * sn;
                s += qsh[d] * k0 + qsh[d + 32] * k1;
            }
        }
        sc[j] = s;
        lmax = fmaxf(lmax, s);
    }
    #pragma unroll
    for (int off = 16; off; off >>= 1) lmax = fmaxf(lmax, __shfl_xor_sync(0xffffffffu, lmax, off));
    if ((tid & 31) == 0) red[tid >> 5] = lmax;
    __syncthreads();
    if (tid == 0) {
        float m = red[0];
        #pragma unroll
        for (int w = 1; w < 8; w++) m = fmaxf(m, red[w]);
        red[0] = m;
    }
    __syncthreads();
    float m = red[0];
    __syncthreads();

    // pass 2: exp + sum
    float lsum = 0.f;
    for (int j = tid; j < TT; j += 256) {
        float p = expf(sc[j] - m);   // masked -1e30 -> exp(-huge) = 0
        sc[j] = p;
        lsum += p;
    }
    #pragma unroll
    for (int off = 16; off; off >>= 1) lsum += __shfl_xor_sync(0xffffffffu, lsum, off);
    if ((tid & 31) == 0) red[tid >> 5] = lsum;
    __syncthreads();
    if (tid == 0) {
        float l = 0.f;
        #pragma unroll
        for (int w = 0; w < 8; w++) l += red[w];
        red[0] = 1.0f / l;
    }
    __syncthreads();
    float il = red[0];

    // pass 3: A @ V   (thread = (chunk, d); 4 chunks of 512 keys)
    int d = tid & 63, chunk = tid >> 6;
    float a = 0.f;
    for (int j = chunk * 512; j < chunk * 512 + 512; j++)
        a += sc[j] * v[(size_t)j * (NKV * HD) + kvh * HD + d];
    accs[chunk][d] = a;
    __syncthreads();
    if (tid < 64)
        out[(size_t)i * (NH * HD) + h * HD + tid] =
            (accs[0][tid] + accs[1][tid] + accs[2][tid] + accs[3][tid]) * il;
}

// ---------------- generic SGEMM 128x128x8, 256 thr, 8x8/thread ----------------
template <bool NT, bool ADD>
__global__ void __launch_bounds__(256) sgemm_kernel(const float* __restrict__ A,
                                                    const float* __restrict__ B,
                                                    float* __restrict__ C,
                                                    int M, int N, int K) {
    __shared__ float As[8][128];
    __shared__ float Bs[8][128];
    const int tid = threadIdx.x;
    const int m0 = blockIdx.y * 128, n0 = blockIdx.x * 128;
    const int tx = tid & 15, ty = tid >> 4;
    const int arow = tid >> 1, ak = (tid & 1) * 4;
    const int bkr = tid >> 5, bn = (tid & 31) * 4;
    float acc[8][8];
    #pragma unroll
    for (int i = 0; i < 8; i++)
        #pragma unroll
        for (int j = 0; j < 8; j++) acc[i][j] = 0.f;
    const float* Aptr = A + (size_t)(m0 + arow) * K + ak;
    for (int k0 = 0; k0 < K; k0 += 8) {
        float4 av = *(const float4*)(Aptr + k0);
        As[ak + 0][arow] = av.x; As[ak + 1][arow] = av.y;
        As[ak + 2][arow] = av.z; As[ak + 3][arow] = av.w;
        if (!NT) {
            float4 bv = *(const float4*)(B + (size_t)(k0 + bkr) * N + n0 + bn);
            *(float4*)&Bs[bkr][bn] = bv;
        } else {
            float4 bv = *(const float4*)(B + (size_t)(n0 + arow) * K + k0 + ak);
            Bs[ak + 0][arow] = bv.x; Bs[ak + 1][arow] = bv.y;
            Bs[ak + 2][arow] = bv.z; Bs[ak + 3][arow] = bv.w;
        }
        __syncthreads();
        #pragma unroll
        for (int kk = 0; kk < 8; kk++) {
            float ra[8], rb[8];
            *(float4*)&ra[0] = *(const float4*)&As[kk][ty * 8];
            *(float4*)&ra[4] = *(const float4*)&As[kk][ty * 8 + 4];
            *(float4*)&rb[0] = *(const float4*)&Bs[kk][tx * 8];
            *(float4*)&rb[4] = *(const float4*)&Bs[kk][tx * 8 + 4];
            #pragma unroll
            for (int i = 0; i < 8; i++)
                #pragma unroll
                for (int j = 0; j < 8; j++) acc[i][j] += ra[i] * rb[j];
        }
        __syncthreads();
    }
    #pragma unroll
    for (int i = 0; i < 8; i++) {
        size_t cb = (size_t)(m0 + ty * 8 + i) * N + n0 + tx * 8;
        if (ADD) {
            #pragma unroll
            for (int j = 0; j < 8; j++) C[cb + j] += acc[i][j];
        } else {
            *(float4*)&C[cb]     = make_float4(acc[i][0], acc[i][1], acc[i][2], acc[i][3]);
            *(float4*)&C[cb + 4] = make_float4(acc[i][4], acc[i][5], acc[i][6], acc[i][7]);
        }
    }
}

// ---------------- routing (dense combine weights) ----------------
__global__ void reset_router_kernel() {
    if (threadIdx.x < NE) { g_counts[threadIdx.x] = 0; g_probsum[threadIdx.x] = 0.f; }
}
__global__ void reset_aux_kernel() { g_aux = 0.f; }
__global__ void zero_w_kernel() {
    int idx = blockIdx.x * 256 + threadIdx.x;
    if (idx < TT * NE) g_w[idx] = 0.f;
}

__global__ void router_kernel(const float* __restrict__ X, const float* __restrict__ RW) {
    int n = blockIdx.x, tid = threadIdx.x;
    const float* xr = X + (size_t)n * DD;
    float p[NE];
    #pragma unroll
    for (int e = 0; e < NE; e++) p[e] = 0.f;
    for (int d = tid; d < DD; d += 256) {
        float xv = xr[d];
        #pragma unroll
        for (int e = 0; e < NE; e++) p[e] += xv * RW[d * NE + e];
    }
    #pragma unroll
    for (int e = 0; e < NE; e++)
        #pragma unroll
        for (int off = 16; off; off >>= 1) p[e] += __shfl_down_sync(0xffffffffu, p[e], off);
    __shared__ float sred[8][NE];
    int warp = tid >> 5, lane = tid & 31;
    if (lane == 0)
        #pragma unroll
        for (int e = 0; e < NE; e++) sred[warp][e] = p[e];
    __syncthreads();
    if (tid == 0) {
        float lg[NE];
        #pragma unroll
        for (int e = 0; e < NE; e++) {
            float s = 0.f;
            #pragma unroll
            for (int w = 0; w < 8; w++) s += sred[w][e];
            lg[e] = s;
        }
        float mx = lg[0];
        #pragma unroll
        for (int e = 1; e < NE; e++) mx = fmaxf(mx, lg[e]);
        float pb[NE], sum = 0.f;
        #pragma unroll
        for (int e = 0; e < NE; e++) { pb[e] = expf(lg[e] - mx); sum += pb[e]; }
        float isum = 1.f / sum;
        #pragma unroll
        for (int e = 0; e < NE; e++) pb[e] *= isum;
        int e1 = 0;
        #pragma unroll
        for (int e = 1; e < NE; e++) if (pb[e] > pb[e1]) e1 = e;
        int e2 = (e1 == 0) ? 1 : 0;
        #pragma unroll
        for (int e = 0; e < NE; e++) if (e != e1 && pb[e] > pb[e2]) e2 = e;
        float s2 = pb[e1] + pb[e2];
        g_w[n * NE + e1] = pb[e1] / s2;
        g_w[n * NE + e2] = pb[e2] / s2;
        atomicAdd(&g_counts[e1], 1);
        atomicAdd(&g_counts[e2], 1);
        #pragma unroll
        for (int e = 0; e < NE; e++) atomicAdd(&g_probsum[e], pb[e]);
    }
}

__global__ void aux_kernel() {
    float s = 0.f;
    #pragma unroll
    for (int e = 0; e < NE; e++) s += g_probsum[e] * (float)g_counts[e];
    g_aux += (float)NE * s / ((float)TT * (float)TT);
}

// ---------------- dense MoE elementwise + combine ----------------
__global__ void silu_mul_kernel() {
    size_t i = (size_t)blockIdx.x * 256 + threadIdx.x;   // NE*TT*FF total
    float g = g_gate[i];
    g_gate[i] = g / (1.f + expf(-g)) * g_up[i];
}

__global__ void combine_dense_kernel(float* __restrict__ x) {
    int n = blockIdx.x;
    float w[NE];
    #pragma unroll
    for (int e = 0; e < NE; e++) w[e] = g_w[n * NE + e];
    for (int d = threadIdx.x; d < DD; d += 256) {
        float s = 0.f;
        #pragma unroll
        for (int e = 0; e < NE; e++)
            s += w[e] * g_y[((size_t)e * TT + n) * DD + d];
        x[(size_t)n * DD + d] += s;
    }
}

__global__ void write_aux_kernel(float* __restrict__ out) { out[(size_t)TT * VV] = g_aux; }

// ---------------- launch ----------------
extern "C" void kernel_launch(void* const* d_in, const int* in_sizes, int n_in,
                              void* d_out, int out_size) {
    const int*   tokens = (const int*)d_in[0];
    const float* emb    = (const float*)d_in[1];
    const float* n1w    = (const float*)d_in[2];
    const float* n2w    = (const float*)d_in[3];
    const float* wq     = (const float*)d_in[4];
    const float* wk     = (const float*)d_in[5];
    const float* wv     = (const float*)d_in[6];
    const float* wo     = (const float*)d_in[7];
    const float* rw     = (const float*)d_in[8];
    const float* wg     = (const float*)d_in[9];
    const float* wu     = (const float*)d_in[10];
    const float* wd     = (const float*)d_in[11];
    const float* now    = (const float*)d_in[12];
    float* out = (float*)d_out;

    float *px, *ph, *pq, *pk, *pv, *pa, *pup, *pgt, *py;
    cudaGetSymbolAddress((void**)&px, g_x);
    cudaGetSymbolAddress((void**)&ph, g_h);
    cudaGetSymbolAddress((void**)&pq, g_q);
    cudaGetSymbolAddress((void**)&pk, g_k);
    cudaGetSymbolAddress((void**)&pv, g_v);
    cudaGetSymbolAddress((void**)&pa, g_attn);
    cudaGetSymbolAddress((void**)&pup, g_up);
    cudaGetSymbolAddress((void**)&pgt, g_gate);
    cudaGetSymbolAddress((void**)&py, g_y);

    embed_kernel<<<TT * DD / 256, 256>>>(tokens, emb, px);
    rope_table_kernel<<<TT * 32 / 256, 256>>>();
    reset_aux_kernel<<<1, 1>>>();

    for (int l = 0; l < 2; l++) {
        rmsnorm_kernel<<<TT, 256>>>(px, n1w + (size_t)l * DD, ph);
        sgemm_kernel<false, false><<<dim3((NH * HD) / 128, TT / 128), 256>>>(
            ph, wq + (size_t)l * DD * NH * HD, pq, TT, NH * HD, DD);
        sgemm_kernel<false, false><<<dim3((NKV * HD) / 128, TT / 128), 256>>>(
            ph, wk + (size_t)l * DD * NKV * HD, pk, TT, NKV * HD, DD);
        sgemm_kernel<false, false><<<dim3((NKV * HD) / 128, TT / 128), 256>>>(
            ph, wv + (size_t)l * DD * NKV * HD, pv, TT, NKV * HD, DD);
        attn_naive_kernel<<<dim3(TT, NH), 256>>>(pq, pk, pv, pa);
        sgemm_kernel<false, true><<<dim3(DD / 128, TT / 128), 256>>>(
            pa, wo + (size_t)l * NH * HD * DD, px, TT, DD, NH * HD);

        rmsnorm_kernel<<<TT, 256>>>(px, n2w + (size_t)l * DD, ph);
        zero_w_kernel<<<(TT * NE + 255) / 256, 256>>>();
        reset_router_kernel<<<1, 32>>>();
        router_kernel<<<TT, 256>>>(ph, rw + (size_t)l * DD * NE);
        aux_kernel<<<1, 1>>>();

        // dense MoE: all experts, weighted combine (mirrors reference einsum)
        for (int e = 0; e < NE; e++) {
            const float* wge = wg + (size_t)l * NE * DD * FF + (size_t)e * DD * FF;
            const float* wue = wu + (size_t)l * NE * DD * FF + (size_t)e * DD * FF;
            sgemm_kernel<false, false><<<dim3(FF / 128, TT / 128), 256>>>(
                ph, wge, pgt + (size_t)e * TT * FF, TT, FF, DD);
            sgemm_kernel<false, false><<<dim3(FF / 128, TT / 128), 256>>>(
                ph, wue, pup + (size_t)e * TT * FF, TT, FF, DD);
        }
        silu_mul_kernel<<<(int)(((size_t)NE * TT * FF) / 256), 256>>>();
        for (int e = 0; e < NE; e++) {
            const float* wde = wd + (size_t)l * NE * FF * DD + (size_t)e * FF * DD;
            sgemm_kernel<false, false><<<dim3(DD / 128, TT / 128), 256>>>(
                pgt + (size_t)e * TT * FF, wde, py + (size_t)e * TT * DD, TT, DD, FF);
        }
        combine_dense_kernel<<<TT, 256>>>(px);
    }

    rmsnorm_kernel<<<TT, 256>>>(px, now, ph);
    sgemm_kernel<true, false><<<dim3(VV / 128, TT / 128), 256>>>(ph, emb, out, TT, VV, DD);
    if (out_size > TT * VV) write_aux_kernel<<<1, 1>>>(out);
}

// round 8
// speedup vs baseline: 1.3189x; 1.3189x over previous
#include <cuda_runtime.h>
#include <math.h>

#define TT 2048
#define DD 1024
#define NH 16
#define NKV 4
#define HD 64
#define NE 8
#define FF 2048
#define VV 32000
#define WIN 1024
#define NGLB 32

// ---------------- scratch (device globals; allocation-free) ----------------
__device__ float g_x[TT * DD];
__device__ float g_h[TT * DD];
__device__ float g_q[TT * NH * HD];
__device__ float g_k[TT * NKV * HD];
__device__ float g_v[TT * NKV * HD];
__device__ float g_attn[TT * DD];
__device__ float g_cos[TT * 32];
__device__ float g_sin[TT * 32];
__device__ float g_ubuf[NE * TT * FF];   // up-proj per packed expert-row
__device__ float g_abuf[NE * TT * FF];   // silu(gate)*up per packed expert-row
__device__ float g_yslot[TT * 2 * DD];   // per (token,k) weighted expert output
__device__ float g_wslot[TT * 2];
__device__ int   g_idxl[NE * TT];        // packed (token<<1)|k
__device__ int   g_counts[NE];
__device__ float g_probsum[NE];
__device__ float g_aux;

// ---------------- small kernels ----------------
__global__ void embed_kernel(const int* __restrict__ tok, const float* __restrict__ emb,
                             float* __restrict__ x) {
    int idx = blockIdx.x * 256 + threadIdx.x;   // TT*DD total
    int t = idx >> 10, d = idx & 1023;
    x[idx] = emb[(size_t)tok[t] * DD + d];
}

__global__ void rope_table_kernel() {
    int idx = blockIdx.x * 256 + threadIdx.x;   // TT*32 total
    int t = idx >> 5, i = idx & 31;
    float inv = 1.0f / powf(500000.0f, (float)(2 * i) * (1.0f / 64.0f));
    float ang = (float)t * inv;
    g_cos[idx] = cosf(ang);
    g_sin[idx] = sinf(ang);
}

__global__ void rmsnorm_kernel(const float* __restrict__ x, const float* __restrict__ w,
                               float* __restrict__ o) {
    int t = blockIdx.x, tid = threadIdx.x;
    const float* xr = x + (size_t)t * DD;
    float ss = 0.f;
    for (int d = tid; d < DD; d += 256) { float v = xr[d]; ss += v * v; }
    #pragma unroll
    for (int off = 16; off; off >>= 1) ss += __shfl_down_sync(0xffffffffu, ss, off);
    __shared__ float sred[8];
    __shared__ float sinv;
    if ((tid & 31) == 0) sred[tid >> 5] = ss;
    __syncthreads();
    if (tid == 0) {
        float tot = 0.f;
        #pragma unroll
        for (int i = 0; i < 8; i++) tot += sred[i];
        sinv = rsqrtf(tot * (1.0f / DD) + 1.1920929e-07f);
    }
    __syncthreads();
    float inv = sinv;
    for (int d = tid; d < DD; d += 256) o[(size_t)t * DD + d] = xr[d] * inv * w[d];
}

// ---------------- naive exact attention (verified): one block per (query, head) ----------------
__global__ void __launch_bounds__(256) attn_naive_kernel(const float* __restrict__ q,
                                                         const float* __restrict__ k,
                                                         const float* __restrict__ v,
                                                         float* __restrict__ out) {
    int i = blockIdx.x, h = blockIdx.y, kvh = h >> 2;
    int tid = threadIdx.x;
    __shared__ float qsh[64];
    __shared__ float sc[TT];
    __shared__ float red[8];
    __shared__ float accs[4][64];

    if (tid < 32) {
        float c = g_cos[i * 32 + tid], s = g_sin[i * 32 + tid];
        float a = q[(size_t)i * (NH * HD) + h * HD + tid];
        float b = q[(size_t)i * (NH * HD) + h * HD + tid + 32];
        qsh[tid]      = (a * c - b * s) * 0.125f;
        qsh[tid + 32] = (b * c + a * s) * 0.125f;
    }
    __syncthreads();

    // pass 1: scores (with inline k-rope) + max
    float lmax = -1e30f;
    for (int j = tid; j < TT; j += 256) {
        bool ok = (j <= i) && ((i - j) < WIN || j < NGLB);
        float s = -1e30f;
        if (ok) {
            const float* kr = k + (size_t)j * (NKV * HD) + kvh * HD;
            const float* cj = g_cos + j * 32;
            const float* sj = g_sin + j * 32;
            s = 0.f;
            #pragma unroll
            for (int d = 0; d < 32; d++) {
                float c = cj[d], sn = sj[d];
                float ka = kr[d], kb = kr[d + 32];
                float k0 = ka * c - kb * sn;
                float k1 = kb * c + ka * sn;
                s += qsh[d] * k0 + qsh[d + 32] * k1;
            }
        }
        sc[j] = s;
        lmax = fmaxf(lmax, s);
    }
    #pragma unroll
    for (int off = 16; off; off >>= 1) lmax = fmaxf(lmax, __shfl_xor_sync(0xffffffffu, lmax, off));
    if ((tid & 31) == 0) red[tid >> 5] = lmax;
    __syncthreads();
    if (tid == 0) {
        float m = red[0];
        #pragma unroll
        for (int w = 1; w < 8; w++) m = fmaxf(m, red[w]);
        red[0] = m;
    }
    __syncthreads();
    float m = red[0];
    __syncthreads();

    // pass 2: exp + sum
    float lsum = 0.f;
    for (int j = tid; j < TT; j += 256) {
        float p = expf(sc[j] - m);
        sc[j] = p;
        lsum += p;
    }
    #pragma unroll
    for (int off = 16; off; off >>= 1) lsum += __shfl_xor_sync(0xffffffffu, lsum, off);
    if ((tid & 31) == 0) red[tid >> 5] = lsum;
    __syncthreads();
    if (tid == 0) {
        float l = 0.f;
        #pragma unroll
        for (int w = 0; w < 8; w++) l += red[w];
        red[0] = 1.0f / l;
    }
    __syncthreads();
    float il = red[0];

    // pass 3: A @ V
    int d = tid & 63, chunk = tid >> 6;
    float a = 0.f;
    for (int j = chunk * 512; j < chunk * 512 + 512; j++)
        a += sc[j] * v[(size_t)j * (NKV * HD) + kvh * HD + d];
    accs[chunk][d] = a;
    __syncthreads();
    if (tid < 64)
        out[(size_t)i * (NH * HD) + h * HD + tid] =
            (accs[0][tid] + accs[1][tid] + accs[2][tid] + accs[3][tid]) * il;
}

// ---------------- generic SGEMM 128x128x8, 256 thr, 8x8/thread ----------------
template <bool NT, bool ADD>
__global__ void __launch_bounds__(256) sgemm_kernel(const float* __restrict__ A,
                                                    const float* __restrict__ B,
                                                    float* __restrict__ C,
                                                    int M, int N, int K) {
    __shared__ float As[8][128];
    __shared__ float Bs[8][128];
    const int tid = threadIdx.x;
    const int m0 = blockIdx.y * 128, n0 = blockIdx.x * 128;
    const int tx = tid & 15, ty = tid >> 4;
    const int arow = tid >> 1, ak = (tid & 1) * 4;
    const int bkr = tid >> 5, bn = (tid & 31) * 4;
    float acc[8][8];
    #pragma unroll
    for (int i = 0; i < 8; i++)
        #pragma unroll
        for (int j = 0; j < 8; j++) acc[i][j] = 0.f;
    const float* Aptr = A + (size_t)(m0 + arow) * K + ak;
    for (int k0 = 0; k0 < K; k0 += 8) {
        float4 av = *(const float4*)(Aptr + k0);
        As[ak + 0][arow] = av.x; As[ak + 1][arow] = av.y;
        As[ak + 2][arow] = av.z; As[ak + 3][arow] = av.w;
        if (!NT) {
            float4 bv = *(const float4*)(B + (size_t)(k0 + bkr) * N + n0 + bn);
            *(float4*)&Bs[bkr][bn] = bv;
        } else {
            float4 bv = *(const float4*)(B + (size_t)(n0 + arow) * K + k0 + ak);
            Bs[ak + 0][arow] = bv.x; Bs[ak + 1][arow] = bv.y;
            Bs[ak + 2][arow] = bv.z; Bs[ak + 3][arow] = bv.w;
        }
        __syncthreads();
        #pragma unroll
        for (int kk = 0; kk < 8; kk++) {
            float ra[8], rb[8];
            *(float4*)&ra[0] = *(const float4*)&As[kk][ty * 8];
            *(float4*)&ra[4] = *(const float4*)&As[kk][ty * 8 + 4];
            *(float4*)&rb[0] = *(const float4*)&Bs[kk][tx * 8];
            *(float4*)&rb[4] = *(const float4*)&Bs[kk][tx * 8 + 4];
            #pragma unroll
            for (int i = 0; i < 8; i++)
                #pragma unroll
                for (int j = 0; j < 8; j++) acc[i][j] += ra[i] * rb[j];
        }
        __syncthreads();
    }
    #pragma unroll
    for (int i = 0; i < 8; i++) {
        size_t cb = (size_t)(m0 + ty * 8 + i) * N + n0 + tx * 8;
        if (ADD) {
            #pragma unroll
            for (int j = 0; j < 8; j++) C[cb + j] += acc[i][j];
        } else {
            *(float4*)&C[cb]     = make_float4(acc[i][0], acc[i][1], acc[i][2], acc[i][3]);
            *(float4*)&C[cb + 4] = make_float4(acc[i][4], acc[i][5], acc[i][6], acc[i][7]);
        }
    }
}

// ---------------- routing (slot lists; exonerated by R3==R5 bit-identity) ----------------
__global__ void reset_router_kernel() {
    if (threadIdx.x < NE) { g_counts[threadIdx.x] = 0; g_probsum[threadIdx.x] = 0.f; }
}
__global__ void reset_aux_kernel() { g_aux = 0.f; }

__global__ void router_kernel(const float* __restrict__ X, const float* __restrict__ RW) {
    int n = blockIdx.x, tid = threadIdx.x;
    const float* xr = X + (size_t)n * DD;
    float p[NE];
    #pragma unroll
    for (int e = 0; e < NE; e++) p[e] = 0.f;
    for (int d = tid; d < DD; d += 256) {
        float xv = xr[d];
        #pragma unroll
        for (int e = 0; e < NE; e++) p[e] += xv * RW[d * NE + e];
    }
    #pragma unroll
    for (int e = 0; e < NE; e++)
        #pragma unroll
        for (int off = 16; off; off >>= 1) p[e] += __shfl_down_sync(0xffffffffu, p[e], off);
    __shared__ float sred[8][NE];
    int warp = tid >> 5, lane = tid & 31;
    if (lane == 0)
        #pragma unroll
        for (int e = 0; e < NE; e++) sred[warp][e] = p[e];
    __syncthreads();
    if (tid == 0) {
        float lg[NE];
        #pragma unroll
        for (int e = 0; e < NE; e++) {
            float s = 0.f;
            #pragma unroll
            for (int w = 0; w < 8; w++) s += sred[w][e];
            lg[e] = s;
        }
        float mx = lg[0];
        #pragma unroll
        for (int e = 1; e < NE; e++) mx = fmaxf(mx, lg[e]);
        float pb[NE], sum = 0.f;
        #pragma unroll
        for (int e = 0; e < NE; e++) { pb[e] = expf(lg[e] - mx); sum += pb[e]; }
        float isum = 1.f / sum;
        #pragma unroll
        for (int e = 0; e < NE; e++) pb[e] *= isum;
        int e1 = 0;
        #pragma unroll
        for (int e = 1; e < NE; e++) if (pb[e] > pb[e1]) e1 = e;
        int e2 = (e1 == 0) ? 1 : 0;
        #pragma unroll
        for (int e = 0; e < NE; e++) if (e != e1 && pb[e] > pb[e2]) e2 = e;
        float s2 = pb[e1] + pb[e2];
        g_wslot[2 * n]     = pb[e1] / s2;
        g_wslot[2 * n + 1] = pb[e2] / s2;
        int p1 = atomicAdd(&g_counts[e1], 1); g_idxl[e1 * TT + p1] = (n << 1);
        int p2 = atomicAdd(&g_counts[e2], 1); g_idxl[e2 * TT + p2] = (n << 1) | 1;
        #pragma unroll
        for (int e = 0; e < NE; e++) atomicAdd(&g_probsum[e], pb[e]);
    }
}

__global__ void aux_kernel() {
    float s = 0.f;
    #pragma unroll
    for (int e = 0; e < NE; e++) s += g_probsum[e] * (float)g_counts[e];
    g_aux += (float)NE * s / ((float)TT * (float)TT);
}

// ---------------- sparse MoE gather GEMMs ----------------
__global__ void __launch_bounds__(256) moe_up_kernel(const float* __restrict__ X,
                                                     const float* __restrict__ Wu) {
    int e = blockIdx.z;
    int count = g_counts[e];
    int m0 = blockIdx.y * 128;
    if (m0 >= count) return;
    const float* B = Wu + (size_t)e * DD * FF;
    int n0 = blockIdx.x * 128;
    __shared__ float As[8][128];
    __shared__ float Bs[8][128];
    const int tid = threadIdx.x;
    const int tx = tid & 15, ty = tid >> 4;
    const int arow = tid >> 1, ak = (tid & 1) * 4;
    const int bkr = tid >> 5, bn = (tid & 31) * 4;
    int gi = m0 + arow;
    int token = (gi < count) ? (g_idxl[e * TT + gi] >> 1) : 0;
    const float* Aptr = X + (size_t)token * DD + ak;
    float acc[8][8];
    #pragma unroll
    for (int i = 0; i < 8; i++)
        #pragma unroll
        for (int j = 0; j < 8; j++) acc[i][j] = 0.f;
    for (int k0 = 0; k0 < DD; k0 += 8) {
        float4 av = *(const float4*)(Aptr + k0);
        As[ak + 0][arow] = av.x; As[ak + 1][arow] = av.y;
        As[ak + 2][arow] = av.z; As[ak + 3][arow] = av.w;
        float4 bv = *(const float4*)(B + (size_t)(k0 + bkr) * FF + n0 + bn);
        *(float4*)&Bs[bkr][bn] = bv;
        __syncthreads();
        #pragma unroll
        for (int kk = 0; kk < 8; kk++) {
            float ra[8], rb[8];
            *(float4*)&ra[0] = *(const float4*)&As[kk][ty * 8];
            *(float4*)&ra[4] = *(const float4*)&As[kk][ty * 8 + 4];
            *(float4*)&rb[0] = *(const float4*)&Bs[kk][tx * 8];
            *(float4*)&rb[4] = *(const float4*)&Bs[kk][tx * 8 + 4];
            #pragma unroll
            for (int i = 0; i < 8; i++)
                #pragma unroll
                for (int j = 0; j < 8; j++) acc[i][j] += ra[i] * rb[j];
        }
        __syncthreads();
    }
    #pragma unroll
    for (int i = 0; i < 8; i++) {
        int row = m0 + ty * 8 + i;
        if (row < count) {
            size_t cb = ((size_t)e * TT + row) * FF + n0 + tx * 8;
            *(float4*)&g_ubuf[cb]     = make_float4(acc[i][0], acc[i][1], acc[i][2], acc[i][3]);
            *(float4*)&g_ubuf[cb + 4] = make_float4(acc[i][4], acc[i][5], acc[i][6], acc[i][7]);
        }
    }
}

__global__ void __launch_bounds__(256) moe_gate_kernel(const float* __restrict__ X,
                                                       const float* __restrict__ Wg) {
    int e = blockIdx.z;
    int count = g_counts[e];
    int m0 = blockIdx.y * 128;
    if (m0 >= count) return;
    const float* B = Wg + (size_t)e * DD * FF;
    int n0 = blockIdx.x * 128;
    __shared__ float As[8][128];
    __shared__ float Bs[8][128];
    const int tid = threadIdx.x;
    const int tx = tid & 15, ty = tid >> 4;
    const int arow = tid >> 1, ak = (tid & 1) * 4;
    const int bkr = tid >> 5, bn = (tid & 31) * 4;
    int gi = m0 + arow;
    int token = (gi < count) ? (g_idxl[e * TT + gi] >> 1) : 0;
    const float* Aptr = X + (size_t)token * DD + ak;
    float acc[8][8];
    #pragma unroll
    for (int i = 0; i < 8; i++)
        #pragma unroll
        for (int j = 0; j < 8; j++) acc[i][j] = 0.f;
    for (int k0 = 0; k0 < DD; k0 += 8) {
        float4 av = *(const float4*)(Aptr + k0);
        As[ak + 0][arow] = av.x; As[ak + 1][arow] = av.y;
        As[ak + 2][arow] = av.z; As[ak + 3][arow] = av.w;
        float4 bv = *(const float4*)(B + (size_t)(k0 + bkr) * FF + n0 + bn);
        *(float4*)&Bs[bkr][bn] = bv;
        __syncthreads();
        #pragma unroll
        for (int kk = 0; kk < 8; kk++) {
            float ra[8], rb[8];
            *(float4*)&ra[0] = *(const float4*)&As[kk][ty * 8];
            *(float4*)&ra[4] = *(const float4*)&As[kk][ty * 8 + 4];
            *(float4*)&rb[0] = *(const float4*)&Bs[kk][tx * 8];
            *(float4*)&rb[4] = *(const float4*)&Bs[kk][tx * 8 + 4];
            #pragma unroll
            for (int i = 0; i < 8; i++)
                #pragma unroll
                for (int j = 0; j < 8; j++) acc[i][j] += ra[i] * rb[j];
        }
        __syncthreads();
    }
    #pragma unroll
    for (int i = 0; i < 8; i++) {
        int row = m0 + ty * 8 + i;
        if (row < count) {
            size_t cb = ((size_t)e * TT + row) * FF + n0 + tx * 8;
            #pragma unroll
            for (int j = 0; j < 8; j++) {
                float g = acc[i][j];
                g_abuf[cb + j] = g / (1.f + expf(-g)) * g_ubuf[cb + j];
            }
        }
    }
}

__global__ void __launch_bounds__(256) moe_down_kernel(const float* __restrict__ Wd) {
    int e = blockIdx.z;
    int count = g_counts[e];
    int m0 = blockIdx.y * 128;
    if (m0 >= count) return;
    const float* B = Wd + (size_t)e * FF * DD;
    int n0 = blockIdx.x * 128;
    __shared__ float As[8][128];
    __shared__ float Bs[8][128];
    const int tid = threadIdx.x;
    const int tx = tid & 15, ty = tid >> 4;
    const int arow = tid >> 1, ak = (tid & 1) * 4;
    const int bkr = tid >> 5, bn = (tid & 31) * 4;
    int gi = m0 + arow;
    int gir = (gi < count) ? gi : 0;
    const float* Aptr = g_abuf + ((size_t)e * TT + gir) * FF + ak;
    float acc[8][8];
    #pragma unroll
    for (int i = 0; i < 8; i++)
        #pragma unroll
        for (int j = 0; j < 8; j++) acc[i][j] = 0.f;
    for (int k0 = 0; k0 < FF; k0 += 8) {
        float4 av = *(const float4*)(Aptr + k0);
        As[ak + 0][arow] = av.x; As[ak + 1][arow] = av.y;
        As[ak + 2][arow] = av.z; As[ak + 3][arow] = av.w;
        float4 bv = *(const float4*)(B + (size_t)(k0 + bkr) * DD + n0 + bn);
        *(float4*)&Bs[bkr][bn] = bv;
        __syncthreads();
        #pragma unroll
        for (int kk = 0; kk < 8; kk++) {
            float ra[8], rb[8];
            *(float4*)&ra[0] = *(const float4*)&As[kk][ty * 8];
            *(float4*)&ra[4] = *(const float4*)&As[kk][ty * 8 + 4];
            *(float4*)&rb[0] = *(const float4*)&Bs[kk][tx * 8];
            *(float4*)&rb[4] = *(const float4*)&Bs[kk][tx * 8 + 4];
            #pragma unroll
            for (int i = 0; i < 8; i++)
                #pragma unroll
                for (int j = 0; j < 8; j++) acc[i][j] += ra[i] * rb[j];
        }
        __syncthreads();
    }
    #pragma unroll
    for (int i = 0; i < 8; i++) {
        int row = m0 + ty * 8 + i;
        if (row < count) {
            int entry = g_idxl[e * TT + row];
            float wgt = g_wslot[entry];
            size_t cb = (size_t)entry * DD + n0 + tx * 8;
            *(float4*)&g_yslot[cb] = make_float4(acc[i][0] * wgt, acc[i][1] * wgt,
                                                 acc[i][2] * wgt, acc[i][3] * wgt);
            *(float4*)&g_yslot[cb + 4] = make_float4(acc[i][4] * wgt, acc[i][5] * wgt,
                                                     acc[i][6] * wgt, acc[i][7] * wgt);
        }
    }
}

__global__ void combine_kernel(float* __restrict__ x) {
    int n = blockIdx.x;
    for (int d = threadIdx.x; d < DD; d += 256)
        x[(size_t)n * DD + d] += g_yslot[(size_t)(2 * n) * DD + d] +
                                 g_yslot[(size_t)(2 * n + 1) * DD + d];
}

__global__ void write_aux_kernel(float* __restrict__ out) { out[(size_t)TT * VV] = g_aux; }

// ---------------- launch ----------------
extern "C" void kernel_launch(void* const* d_in, const int* in_sizes, int n_in,
                              void* d_out, int out_size) {
    const int*   tokens = (const int*)d_in[0];
    const float* emb    = (const float*)d_in[1];
    const float* n1w    = (const float*)d_in[2];
    const float* n2w    = (const float*)d_in[3];
    const float* wq     = (const float*)d_in[4];
    const float* wk     = (const float*)d_in[5];
    const float* wv     = (const float*)d_in[6];
    const float* wo     = (const float*)d_in[7];
    const float* rw     = (const float*)d_in[8];
    const float* wg     = (const float*)d_in[9];
    const float* wu     = (const float*)d_in[10];
    const float* wd     = (const float*)d_in[11];
    const float* now    = (const float*)d_in[12];
    float* out = (float*)d_out;

    float *px, *ph, *pq, *pk, *pv, *pa;
    cudaGetSymbolAddress((void**)&px, g_x);
    cudaGetSymbolAddress((void**)&ph, g_h);
    cudaGetSymbolAddress((void**)&pq, g_q);
    cudaGetSymbolAddress((void**)&pk, g_k);
    cudaGetSymbolAddress((void**)&pv, g_v);
    cudaGetSymbolAddress((void**)&pa, g_attn);

    embed_kernel<<<TT * DD / 256, 256>>>(tokens, emb, px);
    rope_table_kernel<<<TT * 32 / 256, 256>>>();
    reset_aux_kernel<<<1, 1>>>();

    for (int l = 0; l < 2; l++) {
        rmsnorm_kernel<<<TT, 256>>>(px, n1w + (size_t)l * DD, ph);
        sgemm_kernel<false, false><<<dim3((NH * HD) / 128, TT / 128), 256>>>(
            ph, wq + (size_t)l * DD * NH * HD, pq, TT, NH * HD, DD);
        sgemm_kernel<false, false><<<dim3((NKV * HD) / 128, TT / 128), 256>>>(
            ph, wk + (size_t)l * DD * NKV * HD, pk, TT, NKV * HD, DD);
        sgemm_kernel<false, false><<<dim3((NKV * HD) / 128, TT / 128), 256>>>(
            ph, wv + (size_t)l * DD * NKV * HD, pv, TT, NKV * HD, DD);
        attn_naive_kernel<<<dim3(TT, NH), 256>>>(pq, pk, pv, pa);
        sgemm_kernel<false, true><<<dim3(DD / 128, TT / 128), 256>>>(
            pa, wo + (size_t)l * NH * HD * DD, px, TT, DD, NH * HD);

        rmsnorm_kernel<<<TT, 256>>>(px, n2w + (size_t)l * DD, ph);
        reset_router_kernel<<<1, 32>>>();
        router_kernel<<<TT, 256>>>(ph, rw + (size_t)l * DD * NE);
        aux_kernel<<<1, 1>>>();

        moe_up_kernel<<<dim3(FF / 128, TT / 128, NE), 256>>>(
            ph, wu + (size_t)l * NE * DD * FF);
        moe_gate_kernel<<<dim3(FF / 128, TT / 128, NE), 256>>>(
            ph, wg + (size_t)l * NE * DD * FF);
        moe_down_kernel<<<dim3(DD / 128, TT / 128, NE), 256>>>(
            wd + (size_t)l * NE * FF * DD);
        combine_kernel<<<TT, 256>>>(px);
    }

    rmsnorm_kernel<<<TT, 256>>>(px, now, ph);
    sgemm_kernel<true, false><<<dim3(VV / 128, TT / 128), 256>>>(ph, emb, out, TT, VV, DD);
    if (out_size > TT * VV) write_aux_kernel<<<1, 1>>>(out);
}

// round 10
// speedup vs baseline: 4.6469x; 3.5232x over previous
#include <cuda_runtime.h>
#include <math.h>

#define TT 2048
#define DD 1024
#define NH 16
#define NKV 4
#define HD 64
#define NE 8
#define FF 2048
#define VV 32000
#define WIN 1024
#define NGLB 32

// ---------------- scratch (device globals; allocation-free) ----------------
__device__ float g_x[TT * DD];
__device__ float g_h[TT * DD];
__device__ float g_q[TT * NH * HD];
__device__ float g_k[TT * NKV * HD];
__device__ float g_v[TT * NKV * HD];
__device__ float g_attn[TT * DD];
__device__ float g_cos[TT * 32];
__device__ float g_sin[TT * 32];
__device__ float g_ubuf[NE * TT * FF];   // up-proj per packed expert-row
__device__ float g_abuf[NE * TT * FF];   // silu(gate)*up per packed expert-row
__device__ float g_yslot[TT * 2 * DD];   // per (token,k) weighted expert output
__device__ float g_wslot[TT * 2];
__device__ int   g_idxl[NE * TT];        // packed (token<<1)|k
__device__ int   g_counts[NE];
__device__ float g_probsum[NE];
__device__ float g_aux;

// ---------------- small kernels ----------------
__global__ void embed_kernel(const int* __restrict__ tok, const float* __restrict__ emb,
                             float* __restrict__ x) {
    int idx = blockIdx.x * 256 + threadIdx.x;   // TT*DD total
    int t = idx >> 10, d = idx & 1023;
    x[idx] = emb[(size_t)tok[t] * DD + d];
}

__global__ void rope_table_kernel() {
    int idx = blockIdx.x * 256 + threadIdx.x;   // TT*32 total
    int t = idx >> 5, i = idx & 31;
    float inv = 1.0f / powf(500000.0f, (float)(2 * i) * (1.0f / 64.0f));
    float ang = (float)t * inv;
    g_cos[idx] = cosf(ang);
    g_sin[idx] = sinf(ang);
}

__global__ void rmsnorm_kernel(const float* __restrict__ x, const float* __restrict__ w,
                               float* __restrict__ o) {
    int t = blockIdx.x, tid = threadIdx.x;
    const float* xr = x + (size_t)t * DD;
    float ss = 0.f;
    for (int d = tid; d < DD; d += 256) { float v = xr[d]; ss += v * v; }
    #pragma unroll
    for (int off = 16; off; off >>= 1) ss += __shfl_down_sync(0xffffffffu, ss, off);
    __shared__ float sred[8];
    __shared__ float sinv;
    if ((tid & 31) == 0) sred[tid >> 5] = ss;
    __syncthreads();
    if (tid == 0) {
        float tot = 0.f;
        #pragma unroll
        for (int i = 0; i < 8; i++) tot += sred[i];
        sinv = rsqrtf(tot * (1.0f / DD) + 1.1920929e-07f);
    }
    __syncthreads();
    float inv = sinv;
    for (int d = tid; d < DD; d += 256) o[(size_t)t * DD + d] = xr[d] * inv * w[d];
}

// ---------------- flash attention: 128 queries/block, 32-key smem tiles ----------------
// RoPE applied inline from verified tables: q at register load, k at smem load.
__global__ void __launch_bounds__(128) attn_flash_kernel(const float* __restrict__ q,
                                                         const float* __restrict__ k,
                                                         const float* __restrict__ v,
                                                         float* __restrict__ out) {
    int h = blockIdx.y;
    int qs = blockIdx.x * 128;
    int i = qs + threadIdx.x;
    int kvh = h >> 2;
    __shared__ float Ksh[32][64];
    __shared__ float Vsh[32][64];

    // q with inline rope + scale (verified math from naive kernel)
    float qr[64];
    {
        const float* qrow = q + (size_t)i * (NH * HD) + h * HD;
        const float* ci = g_cos + i * 32;
        const float* si = g_sin + i * 32;
        #pragma unroll
        for (int d = 0; d < 32; d++) {
            float c = ci[d], s = si[d];
            float a = qrow[d], b = qrow[d + 32];
            qr[d]      = (a * c - b * s) * 0.125f;
            qr[d + 32] = (b * c + a * s) * 0.125f;
        }
    }
    float m = -1e30f, l = 0.f;
    float acc[64];
    #pragma unroll
    for (int d = 0; d < 64; d++) acc[d] = 0.f;

    for (int j0 = 0; j0 <= qs + 127; j0 += 32) {
        // skip only tiles invisible to ALL queries in block (verified bound)
        if (j0 >= NGLB && j0 + 31 < qs - WIN + 1) continue;
        // load K (roped) and V tiles
        for (int e = threadIdx.x; e < 32 * 64; e += 128) {
            int jj = e >> 6, d = e & 63;
            int j = j0 + jj;
            const float* kr = k + (size_t)j * (NKV * HD) + kvh * HD;
            float val;
            if (d < 32) {
                float c = g_cos[j * 32 + d], s = g_sin[j * 32 + d];
                val = kr[d] * c - kr[d + 32] * s;
            } else {
                int d2 = d - 32;
                float c = g_cos[j * 32 + d2], s = g_sin[j * 32 + d2];
                val = kr[d] * c + kr[d2] * s;
            }
            Ksh[jj][d] = val;
            Vsh[jj][d] = v[(size_t)j * (NKV * HD) + kvh * HD + d];
        }
        __syncthreads();
        float s[32];
        #pragma unroll
        for (int jj = 0; jj < 32; jj++) {
            float a = 0.f;
            #pragma unroll
            for (int d = 0; d < 64; d++) a += qr[d] * Ksh[jj][d];
            int j = j0 + jj;
            bool ok = (j <= i) && ((i - j) < WIN || j < NGLB);
            s[jj] = ok ? a : -1e30f;
        }
        float mt = -1e30f;
        #pragma unroll
        for (int jj = 0; jj < 32; jj++) mt = fmaxf(mt, s[jj]);
        if (mt > -1e29f) {
            float mn = fmaxf(m, mt);
            float f = expf(m - mn);
            l *= f;
            #pragma unroll
            for (int d = 0; d < 64; d++) acc[d] *= f;
            #pragma unroll
            for (int jj = 0; jj < 32; jj++) {
                float pj = expf(s[jj] - mn);
                l += pj;
                #pragma unroll
                for (int d = 0; d < 64; d++) acc[d] += pj * Vsh[jj][d];
            }
            m = mn;
        }
        __syncthreads();
    }
    float il = 1.0f / l;
    #pragma unroll
    for (int d = 0; d < 64; d++) out[(size_t)i * (NH * HD) + h * HD + d] = acc[d] * il;
}

// ---------------- generic SGEMM 128x128x8, 256 thr, 8x8/thread ----------------
template <bool NT, bool ADD>
__global__ void __launch_bounds__(256) sgemm_kernel(const float* __restrict__ A,
                                                    const float* __restrict__ B,
                                                    float* __restrict__ C,
                                                    int M, int N, int K) {
    __shared__ float As[8][128];
    __shared__ float Bs[8][128];
    const int tid = threadIdx.x;
    const int m0 = blockIdx.y * 128, n0 = blockIdx.x * 128;
    const int tx = tid & 15, ty = tid >> 4;
    const int arow = tid >> 1, ak = (tid & 1) * 4;
    const int bkr = tid >> 5, bn = (tid & 31) * 4;
    float acc[8][8];
    #pragma unroll
    for (int i = 0; i < 8; i++)
        #pragma unroll
        for (int j = 0; j < 8; j++) acc[i][j] = 0.f;
    const float* Aptr = A + (size_t)(m0 + arow) * K + ak;
    for (int k0 = 0; k0 < K; k0 += 8) {
        float4 av = *(const float4*)(Aptr + k0);
        As[ak + 0][arow] = av.x; As[ak + 1][arow] = av.y;
        As[ak + 2][arow] = av.z; As[ak + 3][arow] = av.w;
        if (!NT) {
            float4 bv = *(const float4*)(B + (size_t)(k0 + bkr) * N + n0 + bn);
            *(float4*)&Bs[bkr][bn] = bv;
        } else {
            float4 bv = *(const float4*)(B + (size_t)(n0 + arow) * K + k0 + ak);
            Bs[ak + 0][arow] = bv.x; Bs[ak + 1][arow] = bv.y;
            Bs[ak + 2][arow] = bv.z; Bs[ak + 3][arow] = bv.w;
        }
        __syncthreads();
        #pragma unroll
        for (int kk = 0; kk < 8; kk++) {
            float ra[8], rb[8];
            *(float4*)&ra[0] = *(const float4*)&As[kk][ty * 8];
            *(float4*)&ra[4] = *(const float4*)&As[kk][ty * 8 + 4];
            *(float4*)&rb[0] = *(const float4*)&Bs[kk][tx * 8];
            *(float4*)&rb[4] = *(const float4*)&Bs[kk][tx * 8 + 4];
            #pragma unroll
            for (int i = 0; i < 8; i++)
                #pragma unroll
                for (int j = 0; j < 8; j++) acc[i][j] += ra[i] * rb[j];
        }
        __syncthreads();
    }
    #pragma unroll
    for (int i = 0; i < 8; i++) {
        size_t cb = (size_t)(m0 + ty * 8 + i) * N + n0 + tx * 8;
        if (ADD) {
            #pragma unroll
            for (int j = 0; j < 8; j++) C[cb + j] += acc[i][j];
        } else {
            *(float4*)&C[cb]     = make_float4(acc[i][0], acc[i][1], acc[i][2], acc[i][3]);
            *(float4*)&C[cb + 4] = make_float4(acc[i][4], acc[i][5], acc[i][6], acc[i][7]);
        }
    }
}

// ---------------- routing (slot lists; exonerated by R3==R5 bit-identity) ----------------
__global__ void reset_router_kernel() {
    if (threadIdx.x < NE) { g_counts[threadIdx.x] = 0; g_probsum[threadIdx.x] = 0.f; }
}
__global__ void reset_aux_kernel() { g_aux = 0.f; }

__global__ void router_kernel(const float* __restrict__ X, const float* __restrict__ RW) {
    int n = blockIdx.x, tid = threadIdx.x;
    const float* xr = X + (size_t)n * DD;
    float p[NE];
    #pragma unroll
    for (int e = 0; e < NE; e++) p[e] = 0.f;
    for (int d = tid; d < DD; d += 256) {
        float xv = xr[d];
        #pragma unroll
        for (int e = 0; e < NE; e++) p[e] += xv * RW[d * NE + e];
    }
    #pragma unroll
    for (int e = 0; e < NE; e++)
        #pragma unroll
        for (int off = 16; off; off >>= 1) p[e] += __shfl_down_sync(0xffffffffu, p[e], off);
    __shared__ float sred[8][NE];
    int warp = tid >> 5, lane = tid & 31;
    if (lane == 0)
        #pragma unroll
        for (int e = 0; e < NE; e++) sred[warp][e] = p[e];
    __syncthreads();
    if (tid == 0) {
        float lg[NE];
        #pragma unroll
        for (int e = 0; e < NE; e++) {
            float s = 0.f;
            #pragma unroll
            for (int w = 0; w < 8; w++) s += sred[w][e];
            lg[e] = s;
        }
        float mx = lg[0];
        #pragma unroll
        for (int e = 1; e < NE; e++) mx = fmaxf(mx, lg[e]);
        float pb[NE], sum = 0.f;
        #pragma unroll
        for (int e = 0; e < NE; e++) { pb[e] = expf(lg[e] - mx); sum += pb[e]; }
        float isum = 1.f / sum;
        #pragma unroll
        for (int e = 0; e < NE; e++) pb[e] *= isum;
        int e1 = 0;
        #pragma unroll
        for (int e = 1; e < NE; e++) if (pb[e] > pb[e1]) e1 = e;
        int e2 = (e1 == 0) ? 1 : 0;
        #pragma unroll
        for (int e = 0; e < NE; e++) if (e != e1 && pb[e] > pb[e2]) e2 = e;
        float s2 = pb[e1] + pb[e2];
        g_wslot[2 * n]     = pb[e1] / s2;
        g_wslot[2 * n + 1] = pb[e2] / s2;
        int p1 = atomicAdd(&g_counts[e1], 1); g_idxl[e1 * TT + p1] = (n << 1);
        int p2 = atomicAdd(&g_counts[e2], 1); g_idxl[e2 * TT + p2] = (n << 1) | 1;
        #pragma unroll
        for (int e = 0; e < NE; e++) atomicAdd(&g_probsum[e], pb[e]);
    }
}

__global__ void aux_kernel() {
    float s = 0.f;
    #pragma unroll
    for (int e = 0; e < NE; e++) s += g_probsum[e] * (float)g_counts[e];
    g_aux += (float)NE * s / ((float)TT * (float)TT);
}

// ---------------- sparse MoE gather GEMMs ----------------
__global__ void __launch_bounds__(256) moe_up_kernel(const float* __restrict__ X,
                                                     const float* __restrict__ Wu) {
    int e = blockIdx.z;
    int count = g_counts[e];
    int m0 = blockIdx.y * 128;
    if (m0 >= count) return;
    const float* B = Wu + (size_t)e * DD * FF;
    int n0 = blockIdx.x * 128;
    __shared__ float As[8][128];
    __shared__ float Bs[8][128];
    const int tid = threadIdx.x;
    const int tx = tid & 15, ty = tid >> 4;
    const int arow = tid >> 1, ak = (tid & 1) * 4;
    const int bkr = tid >> 5, bn = (tid & 31) * 4;
    int gi = m0 + arow;
    int token = (gi < count) ? (g_idxl[e * TT + gi] >> 1) : 0;
    const float* Aptr = X + (size_t)token * DD + ak;
    float acc[8][8];
    #pragma unroll
    for (int i = 0; i < 8; i++)
        #pragma unroll
        for (int j = 0; j < 8; j++) acc[i][j] = 0.f;
    for (int k0 = 0; k0 < DD; k0 += 8) {
        float4 av = *(const float4*)(Aptr + k0);
        As[ak + 0][arow] = av.x; As[ak + 1][arow] = av.y;
        As[ak + 2][arow] = av.z; As[ak + 3][arow] = av.w;
        float4 bv = *(const float4*)(B + (size_t)(k0 + bkr) * FF + n0 + bn);
        *(float4*)&Bs[bkr][bn] = bv;
        __syncthreads();
        #pragma unroll
        for (int kk = 0; kk < 8; kk++) {
            float ra[8], rb[8];
            *(float4*)&ra[0] = *(const float4*)&As[kk][ty * 8];
            *(float4*)&ra[4] = *(const float4*)&As[kk][ty * 8 + 4];
            *(float4*)&rb[0] = *(const float4*)&Bs[kk][tx * 8];
            *(float4*)&rb[4] = *(const float4*)&Bs[kk][tx * 8 + 4];
            #pragma unroll
            for (int i = 0; i < 8; i++)
                #pragma unroll
                for (int j = 0; j < 8; j++) acc[i][j] += ra[i] * rb[j];
        }
        __syncthreads();
    }
    #pragma unroll
    for (int i = 0; i < 8; i++) {
        int row = m0 + ty * 8 + i;
        if (row < count) {
            size_t cb = ((size_t)e * TT + row) * FF + n0 + tx * 8;
            *(float4*)&g_ubuf[cb]     = make_float4(acc[i][0], acc[i][1], acc[i][2], acc[i][3]);
            *(float4*)&g_ubuf[cb + 4] = make_float4(acc[i][4], acc[i][5], acc[i][6], acc[i][7]);
        }
    }
}

__global__ void __launch_bounds__(256) moe_gate_kernel(const float* __restrict__ X,
                                                       const float* __restrict__ Wg) {
    int e = blockIdx.z;
    int count = g_counts[e];
    int m0 = blockIdx.y * 128;
    if (m0 >= count) return;
    const float* B = Wg + (size_t)e * DD * FF;
    int n0 = blockIdx.x * 128;
    __shared__ float As[8][128];
    __shared__ float Bs[8][128];
    const int tid = threadIdx.x;
    const int tx = tid & 15, ty = tid >> 4;
    const int arow = tid >> 1, ak = (tid & 1) * 4;
    const int bkr = tid >> 5, bn = (tid & 31) * 4;
    int gi = m0 + arow;
    int token = (gi < count) ? (g_idxl[e * TT + gi] >> 1) : 0;
    const float* Aptr = X + (size_t)token * DD + ak;
    float acc[8][8];
    #pragma unroll
    for (int i = 0; i < 8; i++)
        #pragma unroll
        for (int j = 0; j < 8; j++) acc[i][j] = 0.f;
    for (int k0 = 0; k0 < DD; k0 += 8) {
        float4 av = *(const float4*)(Aptr + k0);
        As[ak + 0][arow] = av.x; As[ak + 1][arow] = av.y;
        As[ak + 2][arow] = av.z; As[ak + 3][arow] = av.w;
        float4 bv = *(const float4*)(B + (size_t)(k0 + bkr) * FF + n0 + bn);
        *(float4*)&Bs[bkr][bn] = bv;
        __syncthreads();
        #pragma unroll
        for (int kk = 0; kk < 8; kk++) {
            float ra[8], rb[8];
            *(float4*)&ra[0] = *(const float4*)&As[kk][ty * 8];
            *(float4*)&ra[4] = *(const float4*)&As[kk][ty * 8 + 4];
            *(float4*)&rb[0] = *(const float4*)&Bs[kk][tx * 8];
            *(float4*)&rb[4] = *(const float4*)&Bs[kk][tx * 8 + 4];
            #pragma unroll
            for (int i = 0; i < 8; i++)
                #pragma unroll
                for (int j = 0; j < 8; j++) acc[i][j] += ra[i] * rb[j];
        }
        __syncthreads();
    }
    #pragma unroll
    for (int i = 0; i < 8; i++) {
        int row = m0 + ty * 8 + i;
        if (row < count) {
            size_t cb = ((size_t)e * TT + row) * FF + n0 + tx * 8;
            #pragma unroll
            for (int j = 0; j < 8; j++) {
                float g = acc[i][j];
                g_abuf[cb + j] = g / (1.f + expf(-g)) * g_ubuf[cb + j];
            }
        }
    }
}

__global__ void __launch_bounds__(256) moe_down_kernel(const float* __restrict__ Wd) {
    int e = blockIdx.z;
    int count = g_counts[e];
    int m0 = blockIdx.y * 128;
    if (m0 >= count) return;
    const float* B = Wd + (size_t)e * FF * DD;
    int n0 = blockIdx.x * 128;
    __shared__ float As[8][128];
    __shared__ float Bs[8][128];
    const int tid = threadIdx.x;
    const int tx = tid & 15, ty = tid >> 4;
    const int arow = tid >> 1, ak = (tid & 1) * 4;
    const int bkr = tid >> 5, bn = (tid & 31) * 4;
    int gi = m0 + arow;
    int gir = (gi < count) ? gi : 0;
    const float* Aptr = g_abuf + ((size_t)e * TT + gir) * FF + ak;
    float acc[8][8];
    #pragma unroll
    for (int i = 0; i < 8; i++)
        #pragma unroll
        for (int j = 0; j < 8; j++) acc[i][j] = 0.f;
    for (int k0 = 0; k0 < FF; k0 += 8) {
        float4 av = *(const float4*)(Aptr + k0);
        As[ak + 0][arow] = av.x; As[ak + 1][arow] = av.y;
        As[ak + 2][arow] = av.z; As[ak + 3][arow] = av.w;
        float4 bv = *(const float4*)(B + (size_t)(k0 + bkr) * DD + n0 + bn);
        *(float4*)&Bs[bkr][bn] = bv;
        __syncthreads();
        #pragma unroll
        for (int kk = 0; kk < 8; kk++) {
            float ra[8], rb[8];
            *(float4*)&ra[0] = *(const float4*)&As[kk][ty * 8];
            *(float4*)&ra[4] = *(const float4*)&As[kk][ty * 8 + 4];
            *(float4*)&rb[0] = *(const float4*)&Bs[kk][tx * 8];
            *(float4*)&rb[4] = *(const float4*)&Bs[kk][tx * 8 + 4];
            #pragma unroll
            for (int i = 0; i < 8; i++)
                #pragma unroll
                for (int j = 0; j < 8; j++) acc[i][j] += ra[i] * rb[j];
        }
        __syncthreads();
    }
    #pragma unroll
    for (int i = 0; i < 8; i++) {
        int row = m0 + ty * 8 + i;
        if (row < count) {
            int entry = g_idxl[e * TT + row];
            float wgt = g_wslot[entry];
            size_t cb = (size_t)entry * DD + n0 + tx * 8;
            *(float4*)&g_yslot[cb] = make_float4(acc[i][0] * wgt, acc[i][1] * wgt,
                                                 acc[i][2] * wgt, acc[i][3] * wgt);
            *(float4*)&g_yslot[cb + 4] = make_float4(acc[i][4] * wgt, acc[i][5] * wgt,
                                                     acc[i][6] * wgt, acc[i][7] * wgt);
        }
    }
}

__global__ void combine_kernel(float* __restrict__ x) {
    int n = blockIdx.x;
    for (int d = threadIdx.x; d < DD; d += 256)
        x[(size_t)n * DD + d] += g_yslot[(size_t)(2 * n) * DD + d] +
                                 g_yslot[(size_t)(2 * n + 1) * DD + d];
}

__global__ void write_aux_kernel(float* __restrict__ out) { out[(size_t)TT * VV] = g_aux; }

// ---------------- launch ----------------
extern "C" void kernel_launch(void* const* d_in, const int* in_sizes, int n_in,
                              void* d_out, int out_size) {
    const int*   tokens = (const int*)d_in[0];
    const float* emb    = (const float*)d_in[1];
    const float* n1w    = (const float*)d_in[2];
    const float* n2w    = (const float*)d_in[3];
    const float* wq     = (const float*)d_in[4];
    const float* wk     = (const float*)d_in[5];
    const float* wv     = (const float*)d_in[6];
    const float* wo     = (const float*)d_in[7];
    const float* rw     = (const float*)d_in[8];
    const float* wg     = (const float*)d_in[9];
    const float* wu     = (const float*)d_in[10];
    const float* wd     = (const float*)d_in[11];
    const float* now    = (const float*)d_in[12];
    float* out = (float*)d_out;

    float *px, *ph, *pq, *pk, *pv, *pa;
    cudaGetSymbolAddress((void**)&px, g_x);
    cudaGetSymbolAddress((void**)&ph, g_h);
    cudaGetSymbolAddress((void**)&pq, g_q);
    cudaGetSymbolAddress((void**)&pk, g_k);
    cudaGetSymbolAddress((void**)&pv, g_v);
    cudaGetSymbolAddress((void**)&pa, g_attn);

    embed_kernel<<<TT * DD / 256, 256>>>(tokens, emb, px);
    rope_table_kernel<<<TT * 32 / 256, 256>>>();
    reset_aux_kernel<<<1, 1>>>();

    for (int l = 0; l < 2; l++) {
        rmsnorm_kernel<<<TT, 256>>>(px, n1w + (size_t)l * DD, ph);
        sgemm_kernel<false, false><<<dim3((NH * HD) / 128, TT / 128), 256>>>(
            ph, wq + (size_t)l * DD * NH * HD, pq, TT, NH * HD, DD);
        sgemm_kernel<false, false><<<dim3((NKV * HD) / 128, TT / 128), 256>>>(
            ph, wk + (size_t)l * DD * NKV * HD, pk, TT, NKV * HD, DD);
        sgemm_kernel<false, false><<<dim3((NKV * HD) / 128, TT / 128), 256>>>(
            ph, wv + (size_t)l * DD * NKV * HD, pv, TT, NKV * HD, DD);
        attn_flash_kernel<<<dim3(TT / 128, NH), 128>>>(pq, pk, pv, pa);
        sgemm_kernel<false, true><<<dim3(DD / 128, TT / 128), 256>>>(
            pa, wo + (size_t)l * NH * HD * DD, px, TT, DD, NH * HD);

        rmsnorm_kernel<<<TT, 256>>>(px, n2w + (size_t)l * DD, ph);
        reset_router_kernel<<<1, 32>>>();
        router_kernel<<<TT, 256>>>(ph, rw + (size_t)l * DD * NE);
        aux_kernel<<<1, 1>>>();

        moe_up_kernel<<<dim3(FF / 128, TT / 128, NE), 256>>>(
            ph, wu + (size_t)l * NE * DD * FF);
        moe_gate_kernel<<<dim3(FF / 128, TT / 128, NE), 256>>>(
            ph, wg + (size_t)l * NE * DD * FF);
        moe_down_kernel<<<dim3(DD / 128, TT / 128, NE), 256>>>(
            wd + (size_t)l * NE * FF * DD);
        combine_kernel<<<TT, 256>>>(px);
    }

    rmsnorm_kernel<<<TT, 256>>>(px, now, ph);
    sgemm_kernel<true, false><<<dim3(VV / 128, TT / 128), 256>>>(ph, emb, out, TT, VV, DD);
    if (out_size > TT * VV) write_aux_kernel<<<1, 1>>>(out);
}

// round 12
// speedup vs baseline: 5.7720x; 1.2421x over previous
#include <cuda_runtime.h>
#include <math.h>
#include <stdint.h>

#define TT 2048
#define DD 1024
#define NH 16
#define NKV 4
#define HD 64
#define NE 8
#define FF 2048
#define VV 32000
#define WIN 1024
#define NGLB 32
#define SMP 136   // smem row pitch (floats): conflict-free fragment loads, 16B aligned

// ---------------- scratch (device globals; allocation-free) ----------------
__device__ float g_x[TT * DD];
__device__ float g_h[TT * DD];
__device__ float g_q[TT * NH * HD];
__device__ float g_k[TT * NKV * HD];
__device__ float g_v[TT * NKV * HD];
__device__ float g_attn[TT * DD];
__device__ float g_cos[TT * 32];
__device__ float g_sin[TT * 32];
__device__ float g_ubuf[NE * TT * FF];
__device__ float g_abuf[NE * TT * FF];
__device__ float g_yslot[TT * 2 * DD];
__device__ float g_wslot[TT * 2];
__device__ int   g_idxl[NE * TT];
__device__ int   g_counts[NE];
__device__ float g_probsum[NE];
__device__ float g_aux;

// ---------------- small kernels ----------------
__global__ void embed_kernel(const int* __restrict__ tok, const float* __restrict__ emb,
                             float* __restrict__ x) {
    int idx = blockIdx.x * 256 + threadIdx.x;
    int t = idx >> 10, d = idx & 1023;
    x[idx] = emb[(size_t)tok[t] * DD + d];
}

__global__ void rope_table_kernel() {
    int idx = blockIdx.x * 256 + threadIdx.x;
    int t = idx >> 5, i = idx & 31;
    float inv = 1.0f / powf(500000.0f, (float)(2 * i) * (1.0f / 64.0f));
    float ang = (float)t * inv;
    g_cos[idx] = cosf(ang);
    g_sin[idx] = sinf(ang);
}

__global__ void rmsnorm_kernel(const float* __restrict__ x, const float* __restrict__ w,
                               float* __restrict__ o) {
    int t = blockIdx.x, tid = threadIdx.x;
    const float* xr = x + (size_t)t * DD;
    float ss = 0.f;
    for (int d = tid; d < DD; d += 256) { float v = xr[d]; ss += v * v; }
    #pragma unroll
    for (int off = 16; off; off >>= 1) ss += __shfl_down_sync(0xffffffffu, ss, off);
    __shared__ float sred[8];
    __shared__ float sinv;
    if ((tid & 31) == 0) sred[tid >> 5] = ss;
    __syncthreads();
    if (tid == 0) {
        float tot = 0.f;
        #pragma unroll
        for (int i = 0; i < 8; i++) tot += sred[i];
        sinv = rsqrtf(tot * (1.0f / DD) + 1.1920929e-07f);
    }
    __syncthreads();
    float inv = sinv;
    for (int d = tid; d < DD; d += 256) o[(size_t)t * DD + d] = xr[d] * inv * w[d];
}

// ---------------- flash attention (verified R10) ----------------
__global__ void __launch_bounds__(128) attn_flash_kernel(const float* __restrict__ q,
                                                         const float* __restrict__ k,
                                                         const float* __restrict__ v,
                                                         float* __restrict__ out) {
    int h = blockIdx.y;
    int qs = blockIdx.x * 128;
    int i = qs + threadIdx.x;
    int kvh = h >> 2;
    __shared__ float Ksh[32][64];
    __shared__ float Vsh[32][64];
    float qr[64];
    {
        const float* qrow = q + (size_t)i * (NH * HD) + h * HD;
        const float* ci = g_cos + i * 32;
        const float* si = g_sin + i * 32;
        #pragma unroll
        for (int d = 0; d < 32; d++) {
            float c = ci[d], s = si[d];
            float a = qrow[d], b = qrow[d + 32];
            qr[d]      = (a * c - b * s) * 0.125f;
            qr[d + 32] = (b * c + a * s) * 0.125f;
        }
    }
    float m = -1e30f, l = 0.f;
    float acc[64];
    #pragma unroll
    for (int d = 0; d < 64; d++) acc[d] = 0.f;

    for (int j0 = 0; j0 <= qs + 127; j0 += 32) {
        if (j0 >= NGLB && j0 + 31 < qs - WIN + 1) continue;
        for (int e = threadIdx.x; e < 32 * 64; e += 128) {
            int jj = e >> 6, d = e & 63;
            int j = j0 + jj;
            const float* kr = k + (size_t)j * (NKV * HD) + kvh * HD;
            float val;
            if (d < 32) {
                float c = g_cos[j * 32 + d], s = g_sin[j * 32 + d];
                val = kr[d] * c - kr[d + 32] * s;
            } else {
                int d2 = d - 32;
                float c = g_cos[j * 32 + d2], s = g_sin[j * 32 + d2];
                val = kr[d] * c + kr[d2] * s;
            }
            Ksh[jj][d] = val;
            Vsh[jj][d] = v[(size_t)j * (NKV * HD) + kvh * HD + d];
        }
        __syncthreads();
        float s[32];
        #pragma unroll
        for (int jj = 0; jj < 32; jj++) {
            float a = 0.f;
            #pragma unroll
            for (int d = 0; d < 64; d++) a += qr[d] * Ksh[jj][d];
            int j = j0 + jj;
            bool ok = (j <= i) && ((i - j) < WIN || j < NGLB);
            s[jj] = ok ? a : -1e30f;
        }
        float mt = -1e30f;
        #pragma unroll
        for (int jj = 0; jj < 32; jj++) mt = fmaxf(mt, s[jj]);
        if (mt > -1e29f) {
            float mn = fmaxf(m, mt);
            float f = expf(m - mn);
            l *= f;
            #pragma unroll
            for (int d = 0; d < 64; d++) acc[d] *= f;
            #pragma unroll
            for (int jj = 0; jj < 32; jj++) {
                float pj = expf(s[jj] - mn);
                l += pj;
                #pragma unroll
                for (int d = 0; d < 64; d++) acc[d] += pj * Vsh[jj][d];
            }
            m = mn;
        }
        __syncthreads();
    }
    float il = 1.0f / l;
    #pragma unroll
    for (int d = 0; d < 64; d++) out[(size_t)i * (NH * HD) + h * HD + d] = acc[d] * il;
}

// ---------------- tf32 3x-split tensor-core GEMM core ----------------
// Block 128x128, BK=16, 256 thr = 8 warps (2Mx4N), warp tile 64x32,
// mma.m16n8k8: 4 M-tiles x 4 N-tiles per warp. Accum fp32.
__device__ __forceinline__ uint32_t cvt_tf32(float x) {
    uint32_t r; asm("cvt.rna.tf32.f32 %0, %1;" : "=r"(r) : "f"(x)); return r;
}

__device__ __forceinline__ void mma8(float* c, uint32_t a0, uint32_t a1, uint32_t a2,
                                     uint32_t a3, uint32_t b0, uint32_t b1) {
    asm volatile(
        "mma.sync.aligned.m16n8k8.row.col.f32.tf32.tf32.f32 "
        "{%0,%1,%2,%3}, {%4,%5,%6,%7}, {%8,%9}, {%0,%1,%2,%3};"
        : "+f"(c[0]), "+f"(c[1]), "+f"(c[2]), "+f"(c[3])
        : "r"(a0), "r"(a1), "r"(a2), "r"(a3), "r"(b0), "r"(b1));
}

// As, Bs: [16][SMP] (k-major). cacc[mt][nt][4].
__device__ __forceinline__ void tf32_block_mma(float (*cacc)[4][4],
                                               const float* As, const float* Bs,
                                               int lane, int wm, int wn) {
    int lr = lane >> 2, lc = lane & 3;
    #pragma unroll
    for (int ks = 0; ks < 16; ks += 8) {
        uint32_t bh[4][2], bl[4][2];
        #pragma unroll
        for (int nt = 0; nt < 4; nt++) {
            float f0 = Bs[(ks + lc) * SMP + wn + nt * 8 + lr];
            float f1 = Bs[(ks + lc + 4) * SMP + wn + nt * 8 + lr];
            bh[nt][0] = cvt_tf32(f0);
            bl[nt][0] = cvt_tf32(f0 - __uint_as_float(bh[nt][0]));
            bh[nt][1] = cvt_tf32(f1);
            bl[nt][1] = cvt_tf32(f1 - __uint_as_float(bh[nt][1]));
        }
        #pragma unroll
        for (int mt = 0; mt < 4; mt++) {
            float a0 = As[(ks + lc) * SMP + wm + mt * 16 + lr];
            float a1 = As[(ks + lc) * SMP + wm + mt * 16 + lr + 8];
            float a2 = As[(ks + lc + 4) * SMP + wm + mt * 16 + lr];
            float a3 = As[(ks + lc + 4) * SMP + wm + mt * 16 + lr + 8];
            uint32_t ah0 = cvt_tf32(a0), ah1 = cvt_tf32(a1);
            uint32_t ah2 = cvt_tf32(a2), ah3 = cvt_tf32(a3);
            uint32_t al0 = cvt_tf32(a0 - __uint_as_float(ah0));
            uint32_t al1 = cvt_tf32(a1 - __uint_as_float(ah1));
            uint32_t al2 = cvt_tf32(a2 - __uint_as_float(ah2));
            uint32_t al3 = cvt_tf32(a3 - __uint_as_float(ah3));
            #pragma unroll
            for (int nt = 0; nt < 4; nt++) {
                mma8(cacc[mt][nt], ah0, ah1, ah2, ah3, bh[nt][0], bh[nt][1]);
                mma8(cacc[mt][nt], al0, al1, al2, al3, bh[nt][0], bh[nt][1]);
                mma8(cacc[mt][nt], ah0, ah1, ah2, ah3, bl[nt][0], bl[nt][1]);
            }
        }
    }
}

#define TG_PROLOG                                                              \
    __shared__ float As[16 * SMP];                                             \
    __shared__ float Bs[16 * SMP];                                             \
    const int tid = threadIdx.x, lane = tid & 31, warp = tid >> 5;             \
    const int wm = (warp >> 2) * 64, wn = (warp & 3) * 32;                     \
    const int t2 = tid * 2;                                                    \
    const int ma0 = t2 >> 2, kca0 = (t2 & 3) * 4;                              \
    const int ma1 = (t2 + 1) >> 2, kca1 = ((t2 + 1) & 3) * 4;                  \
    float cacc[4][4][4];                                                       \
    _Pragma("unroll") for (int i = 0; i < 4; i++)                              \
        _Pragma("unroll") for (int j = 0; j < 4; j++)                          \
            _Pragma("unroll") for (int r = 0; r < 4; r++) cacc[i][j][r] = 0.f;

#define TG_SCATTER_A(av, mm, kc)                                               \
    As[(kc + 0) * SMP + (mm)] = av.x; As[(kc + 1) * SMP + (mm)] = av.y;        \
    As[(kc + 2) * SMP + (mm)] = av.z; As[(kc + 3) * SMP + (mm)] = av.w;

#define TG_SCATTER_B(bv, nn, kc)                                               \
    Bs[(kc + 0) * SMP + (nn)] = bv.x; Bs[(kc + 1) * SMP + (nn)] = bv.y;        \
    Bs[(kc + 2) * SMP + (nn)] = bv.z; Bs[(kc + 3) * SMP + (nn)] = bv.w;

// ---- generic NN (B row-major [K][N]) with optional C += ----
template <bool ADD>
__global__ void __launch_bounds__(256) tgemm_nn_kernel(const float* __restrict__ A,
                                                       const float* __restrict__ B,
                                                       float* __restrict__ C,
                                                       int M, int N, int K) {
    const int m0 = blockIdx.y * 128, n0 = blockIdx.x * 128;
    TG_PROLOG
    const int bkr0 = t2 >> 5, bnc0 = (t2 & 31) * 4;
    const int bkr1 = (t2 + 1) >> 5, bnc1 = ((t2 + 1) & 31) * 4;
    for (int k0 = 0; k0 < K; k0 += 16) {
        float4 av0 = *(const float4*)(A + (size_t)(m0 + ma0) * K + k0 + kca0);
        float4 av1 = *(const float4*)(A + (size_t)(m0 + ma1) * K + k0 + kca1);
        float4 bv0 = *(const float4*)(B + (size_t)(k0 + bkr0) * N + n0 + bnc0);
        float4 bv1 = *(const float4*)(B + (size_t)(k0 + bkr1) * N + n0 + bnc1);
        TG_SCATTER_A(av0, ma0, kca0)
        TG_SCATTER_A(av1, ma1, kca1)
        *(float4*)&Bs[bkr0 * SMP + bnc0] = bv0;
        *(float4*)&Bs[bkr1 * SMP + bnc1] = bv1;
        __syncthreads();
        tf32_block_mma(cacc, As, Bs, lane, wm, wn);
        __syncthreads();
    }
    int lr = lane >> 2, lc = lane & 3;
    #pragma unroll
    for (int mt = 0; mt < 4; mt++) {
        int r0 = m0 + wm + mt * 16 + lr;
        #pragma unroll
        for (int nt = 0; nt < 4; nt++) {
            size_t c0 = (size_t)r0 * N + n0 + wn + nt * 8 + lc * 2;
            size_t c1 = (size_t)(r0 + 8) * N + n0 + wn + nt * 8 + lc * 2;
            if (ADD) {
                C[c0] += cacc[mt][nt][0]; C[c0 + 1] += cacc[mt][nt][1];
                C[c1] += cacc[mt][nt][2]; C[c1 + 1] += cacc[mt][nt][3];
            } else {
                C[c0] = cacc[mt][nt][0]; C[c0 + 1] = cacc[mt][nt][1];
                C[c1] = cacc[mt][nt][2]; C[c1 + 1] = cacc[mt][nt][3];
            }
        }
    }
}

// ---- NT (B row-major [N][K]; lm_head) ----
__global__ void __launch_bounds__(256) tgemm_nt_kernel(const float* __restrict__ A,
                                                       const float* __restrict__ B,
                                                       float* __restrict__ C,
                                                       int M, int N, int K) {
    const int m0 = blockIdx.y * 128, n0 = blockIdx.x * 128;
    TG_PROLOG
    for (int k0 = 0; k0 < K; k0 += 16) {
        float4 av0 = *(const float4*)(A + (size_t)(m0 + ma0) * K + k0 + kca0);
        float4 av1 = *(const float4*)(A + (size_t)(m0 + ma1) * K + k0 + kca1);
        float4 bv0 = *(const float4*)(B + (size_t)(n0 + ma0) * K + k0 + kca0);
        float4 bv1 = *(const float4*)(B + (size_t)(n0 + ma1) * K + k0 + kca1);
        TG_SCATTER_A(av0, ma0, kca0)
        TG_SCATTER_A(av1, ma1, kca1)
        TG_SCATTER_B(bv0, ma0, kca0)
        TG_SCATTER_B(bv1, ma1, kca1)
        __syncthreads();
        tf32_block_mma(cacc, As, Bs, lane, wm, wn);
        __syncthreads();
    }
    int lr = lane >> 2, lc = lane & 3;
    #pragma unroll
    for (int mt = 0; mt < 4; mt++) {
        int r0 = m0 + wm + mt * 16 + lr;
        #pragma unroll
        for (int nt = 0; nt < 4; nt++) {
            size_t c0 = (size_t)r0 * N + n0 + wn + nt * 8 + lc * 2;
            size_t c1 = (size_t)(r0 + 8) * N + n0 + wn + nt * 8 + lc * 2;
            C[c0] = cacc[mt][nt][0]; C[c0 + 1] = cacc[mt][nt][1];
            C[c1] = cacc[mt][nt][2]; C[c1 + 1] = cacc[mt][nt][3];
        }
    }
}

// ---- MoE up: gathered A rows from X, output to g_ubuf ----
__global__ void __launch_bounds__(256) tmoe_up_kernel(const float* __restrict__ X,
                                                      const float* __restrict__ Wu) {
    int e = blockIdx.z;
    int count = g_counts[e];
    int m0 = blockIdx.y * 128;
    if (m0 >= count) return;
    const float* B = Wu + (size_t)e * DD * FF;
    const int n0 = blockIdx.x * 128;
    TG_PROLOG
    const int bkr0 = t2 >> 5, bnc0 = (t2 & 31) * 4;
    const int bkr1 = (t2 + 1) >> 5, bnc1 = ((t2 + 1) & 31) * 4;
    int gi0 = m0 + ma0, gi1 = m0 + ma1;
    const float* ar0 = X + (size_t)((gi0 < count) ? (g_idxl[e * TT + gi0] >> 1) : 0) * DD;
    const float* ar1 = X + (size_t)((gi1 < count) ? (g_idxl[e * TT + gi1] >> 1) : 0) * DD;
    for (int k0 = 0; k0 < DD; k0 += 16) {
        float4 av0 = *(const float4*)(ar0 + k0 + kca0);
        float4 av1 = *(const float4*)(ar1 + k0 + kca1);
        float4 bv0 = *(const float4*)(B + (size_t)(k0 + bkr0) * FF + n0 + bnc0);
        float4 bv1 = *(const float4*)(B + (size_t)(k0 + bkr1) * FF + n0 + bnc1);
        TG_SCATTER_A(av0, ma0, kca0)
        TG_SCATTER_A(av1, ma1, kca1)
        *(float4*)&Bs[bkr0 * SMP + bnc0] = bv0;
        *(float4*)&Bs[bkr1 * SMP + bnc1] = bv1;
        __syncthreads();
        tf32_block_mma(cacc, As, Bs, lane, wm, wn);
        __syncthreads();
    }
    int lr = lane >> 2, lc = lane & 3;
    #pragma unroll
    for (int mt = 0; mt < 4; mt++) {
        int r0 = m0 + wm + mt * 16 + lr;
        #pragma unroll
        for (int nt = 0; nt < 4; nt++) {
            int cn = n0 + wn + nt * 8 + lc * 2;
            if (r0 < count) {
                size_t cb = ((size_t)e * TT + r0) * FF + cn;
                g_ubuf[cb] = cacc[mt][nt][0]; g_ubuf[cb + 1] = cacc[mt][nt][1];
            }
            if (r0 + 8 < count) {
                size_t cb = ((size_t)e * TT + r0 + 8) * FF + cn;
                g_ubuf[cb] = cacc[mt][nt][2]; g_ubuf[cb + 1] = cacc[mt][nt][3];
            }
        }
    }
}

// ---- MoE gate: gathered A rows, epilogue silu(g)*ubuf -> g_abuf ----
__global__ void __launch_bounds__(256) tmoe_gate_kernel(const float* __restrict__ X,
                                                        const float* __restrict__ Wg) {
    int e = blockIdx.z;
    int count = g_counts[e];
    int m0 = blockIdx.y * 128;
    if (m0 >= count) return;
    const float* B = Wg + (size_t)e * DD * FF;
    const int n0 = blockIdx.x * 128;
    TG_PROLOG
    const int bkr0 = t2 >> 5, bnc0 = (t2 & 31) * 4;
    const int bkr1 = (t2 + 1) >> 5, bnc1 = ((t2 + 1) & 31) * 4;
    int gi0 = m0 + ma0, gi1 = m0 + ma1;
    const float* ar0 = X + (size_t)((gi0 < count) ? (g_idxl[e * TT + gi0] >> 1) : 0) * DD;
    const float* ar1 = X + (size_t)((gi1 < count) ? (g_idxl[e * TT + gi1] >> 1) : 0) * DD;
    for (int k0 = 0; k0 < DD; k0 += 16) {
        float4 av0 = *(const float4*)(ar0 + k0 + kca0);
        float4 av1 = *(const float4*)(ar1 + k0 + kca1);
        float4 bv0 = *(const float4*)(B + (size_t)(k0 + bkr0) * FF + n0 + bnc0);
        float4 bv1 = *(const float4*)(B + (size_t)(k0 + bkr1) * FF + n0 + bnc1);
        TG_SCATTER_A(av0, ma0, kca0)
        TG_SCATTER_A(av1, ma1, kca1)
        *(float4*)&Bs[bkr0 * SMP + bnc0] = bv0;
        *(float4*)&Bs[bkr1 * SMP + bnc1] = bv1;
        __syncthreads();
        tf32_block_mma(cacc, As, Bs, lane, wm, wn);
        __syncthreads();
    }
    int lr = lane >> 2, lc = lane & 3;
    #pragma unroll
    for (int mt = 0; mt < 4; mt++) {
        int r0 = m0 + wm + mt * 16 + lr;
        #pragma unroll
        for (int nt = 0; nt < 4; nt++) {
            int cn = n0 + wn + nt * 8 + lc * 2;
            #pragma unroll
            for (int half = 0; half < 2; half++) {
                int row = r0 + half * 8;
                if (row < count) {
                    size_t cb = ((size_t)e * TT + row) * FF + cn;
                    float ga = cacc[mt][nt][half * 2];
                    float gb = cacc[mt][nt][half * 2 + 1];
                    g_abuf[cb]     = ga / (1.f + expf(-ga)) * g_ubuf[cb];
                    g_abuf[cb + 1] = gb / (1.f + expf(-gb)) * g_ubuf[cb + 1];
                }
            }
        }
    }
}

// ---- MoE down: A rows from g_abuf, weighted scatter to g_yslot ----
__global__ void __launch_bounds__(256) tmoe_down_kernel(const float* __restrict__ Wd) {
    int e = blockIdx.z;
    int count = g_counts[e];
    int m0 = blockIdx.y * 128;
    if (m0 >= count) return;
    const float* B = Wd + (size_t)e * FF * DD;
    const int n0 = blockIdx.x * 128;
    TG_PROLOG
    const int bkr0 = t2 >> 5, bnc0 = (t2 & 31) * 4;
    const int bkr1 = (t2 + 1) >> 5, bnc1 = ((t2 + 1) & 31) * 4;
    int gi0 = m0 + ma0, gi1 = m0 + ma1;
    const float* ar0 = g_abuf + ((size_t)e * TT + ((gi0 < count) ? gi0 : 0)) * FF;
    const float* ar1 = g_abuf + ((size_t)e * TT + ((gi1 < count) ? gi1 : 0)) * FF;
    for (int k0 = 0; k0 < FF; k0 += 16) {
        float4 av0 = *(const float4*)(ar0 + k0 + kca0);
        float4 av1 = *(const float4*)(ar1 + k0 + kca1);
        float4 bv0 = *(const float4*)(B + (size_t)(k0 + bkr0) * DD + n0 + bnc0);
        float4 bv1 = *(const float4*)(B + (size_t)(k0 + bkr1) * DD + n0 + bnc1);
        TG_SCATTER_A(av0, ma0, kca0)
        TG_SCATTER_A(av1, ma1, kca1)
        *(float4*)&Bs[bkr0 * SMP + bnc0] = bv0;
        *(float4*)&Bs[bkr1 * SMP + bnc1] = bv1;
        __syncthreads();
        tf32_block_mma(cacc, As, Bs, lane, wm, wn);
        __syncthreads();
    }
    int lr = lane >> 2, lc = lane & 3;
    #pragma unroll
    for (int mt = 0; mt < 4; mt++) {
        int r0 = m0 + wm + mt * 16 + lr;
        #pragma unroll
        for (int half = 0; half < 2; half++) {
            int row = r0 + half * 8;
            if (row < count) {
                int entry = g_idxl[e * TT + row];
                float wgt = g_wslot[entry];
                #pragma unroll
                for (int nt = 0; nt < 4; nt++) {
                    int cn = n0 + wn + nt * 8 + lc * 2;
                    size_t cb = (size_t)entry * DD + cn;
                    g_yslot[cb]     = cacc[mt][nt][half * 2] * wgt;
                    g_yslot[cb + 1] = cacc[mt][nt][half * 2 + 1] * wgt;
                }
            }
        }
    }
}

// ---------------- routing (verified) ----------------
__global__ void reset_router_kernel() {
    if (threadIdx.x < NE) { g_counts[threadIdx.x] = 0; g_probsum[threadIdx.x] = 0.f; }
}
__global__ void reset_aux_kernel() { g_aux = 0.f; }

__global__ void router_kernel(const float* __restrict__ X, const float* __restrict__ RW) {
    int n = blockIdx.x, tid = threadIdx.x;
    const float* xr = X + (size_t)n * DD;
    float p[NE];
    #pragma unroll
    for (int e = 0; e < NE; e++) p[e] = 0.f;
    for (int d = tid; d < DD; d += 256) {
        float xv = xr[d];
        #pragma unroll
        for (int e = 0; e < NE; e++) p[e] += xv * RW[d * NE + e];
    }
    #pragma unroll
    for (int e = 0; e < NE; e++)
        #pragma unroll
        for (int off = 16; off; off >>= 1) p[e] += __shfl_down_sync(0xffffffffu, p[e], off);
    __shared__ float sred[8][NE];
    int warp = tid >> 5, lane = tid & 31;
    if (lane == 0)
        #pragma unroll
        for (int e = 0; e < NE; e++) sred[warp][e] = p[e];
    __syncthreads();
    if (tid == 0) {
        float lg[NE];
        #pragma unroll
        for (int e = 0; e < NE; e++) {
            float s = 0.f;
            #pragma unroll
            for (int w = 0; w < 8; w++) s += sred[w][e];
            lg[e] = s;
        }
        float mx = lg[0];
        #pragma unroll
        for (int e = 1; e < NE; e++) mx = fmaxf(mx, lg[e]);
        float pb[NE], sum = 0.f;
        #pragma unroll
        for (int e = 0; e < NE; e++) { pb[e] = expf(lg[e] - mx); sum += pb[e]; }
        float isum = 1.f / sum;
        #pragma unroll
        for (int e = 0; e < NE; e++) pb[e] *= isum;
        int e1 = 0;
        #pragma unroll
        for (int e = 1; e < NE; e++) if (pb[e] > pb[e1]) e1 = e;
        int e2 = (e1 == 0) ? 1 : 0;
        #pragma unroll
        for (int e = 0; e < NE; e++) if (e != e1 && pb[e] > pb[e2]) e2 = e;
        float s2 = pb[e1] + pb[e2];
        g_wslot[2 * n]     = pb[e1] / s2;
        g_wslot[2 * n + 1] = pb[e2] / s2;
        int p1 = atomicAdd(&g_counts[e1], 1); g_idxl[e1 * TT + p1] = (n << 1);
        int p2 = atomicAdd(&g_counts[e2], 1); g_idxl[e2 * TT + p2] = (n << 1) | 1;
        #pragma unroll
        for (int e = 0; e < NE; e++) atomicAdd(&g_probsum[e], pb[e]);
    }
}

__global__ void aux_kernel() {
    float s = 0.f;
    #pragma unroll
    for (int e = 0; e < NE; e++) s += g_probsum[e] * (float)g_counts[e];
    g_aux += (float)NE * s / ((float)TT * (float)TT);
}

__global__ void combine_kernel(float* __restrict__ x) {
    int n = blockIdx.x;
    for (int d = threadIdx.x; d < DD; d += 256)
        x[(size_t)n * DD + d] += g_yslot[(size_t)(2 * n) * DD + d] +
                                 g_yslot[(size_t)(2 * n + 1) * DD + d];
}

__global__ void write_aux_kernel(float* __restrict__ out) { out[(size_t)TT * VV] = g_aux; }

// ---------------- launch ----------------
extern "C" void kernel_launch(void* const* d_in, const int* in_sizes, int n_in,
                              void* d_out, int out_size) {
    const int*   tokens = (const int*)d_in[0];
    const float* emb    = (const float*)d_in[1];
    const float* n1w    = (const float*)d_in[2];
    const float* n2w    = (const float*)d_in[3];
    const float* wq     = (const float*)d_in[4];
    const float* wk     = (const float*)d_in[5];
    const float* wv     = (const float*)d_in[6];
    const float* wo     = (const float*)d_in[7];
    const float* rw     = (const float*)d_in[8];
    const float* wg     = (const float*)d_in[9];
    const float* wu     = (const float*)d_in[10];
    const float* wd     = (const float*)d_in[11];
    const float* now    = (const float*)d_in[12];
    float* out = (float*)d_out;

    float *px, *ph, *pq, *pk, *pv, *pa;
    cudaGetSymbolAddress((void**)&px, g_x);
    cudaGetSymbolAddress((void**)&ph, g_h);
    cudaGetSymbolAddress((void**)&pq, g_q);
    cudaGetSymbolAddress((void**)&pk, g_k);
    cudaGetSymbolAddress((void**)&pv, g_v);
    cudaGetSymbolAddress((void**)&pa, g_attn);

    embed_kernel<<<TT * DD / 256, 256>>>(tokens, emb, px);
    rope_table_kernel<<<TT * 32 / 256, 256>>>();
    reset_aux_kernel<<<1, 1>>>();

    for (int l = 0; l < 2; l++) {
        rmsnorm_kernel<<<TT, 256>>>(px, n1w + (size_t)l * DD, ph);
        tgemm_nn_kernel<false><<<dim3((NH * HD) / 128, TT / 128), 256>>>(
            ph, wq + (size_t)l * DD * NH * HD, pq, TT, NH * HD, DD);
        tgemm_nn_kernel<false><<<dim3((NKV * HD) / 128, TT / 128), 256>>>(
            ph, wk + (size_t)l * DD * NKV * HD, pk, TT, NKV * HD, DD);
        tgemm_nn_kernel<false><<<dim3((NKV * HD) / 128, TT / 128), 256>>>(
            ph, wv + (size_t)l * DD * NKV * HD, pv, TT, NKV * HD, DD);
        attn_flash_kernel<<<dim3(TT / 128, NH), 128>>>(pq, pk, pv, pa);
        tgemm_nn_kernel<true><<<dim3(DD / 128, TT / 128), 256>>>(
            pa, wo + (size_t)l * NH * HD * DD, px, TT, DD, NH * HD);

        rmsnorm_kernel<<<TT, 256>>>(px, n2w + (size_t)l * DD, ph);
        reset_router_kernel<<<1, 32>>>();
        router_kernel<<<TT, 256>>>(ph, rw + (size_t)l * DD * NE);
        aux_kernel<<<1, 1>>>();

        tmoe_up_kernel<<<dim3(FF / 128, TT / 128, NE), 256>>>(
            ph, wu + (size_t)l * NE * DD * FF);
        tmoe_gate_kernel<<<dim3(FF / 128, TT / 128, NE), 256>>>(
            ph, wg + (size_t)l * NE * DD * FF);
        tmoe_down_kernel<<<dim3(DD / 128, TT / 128, NE), 256>>>(
            wd + (size_t)l * NE * FF * DD);
        combine_kernel<<<TT, 256>>>(px);
    }

    rmsnorm_kernel<<<TT, 256>>>(px, now, ph);
    tgemm_nt_kernel<<<dim3(VV / 128, TT / 128), 256>>>(ph, emb, out, TT, VV, DD);
    if (out_size > TT * VV) write_aux_kernel<<<1, 1>>>(out);
}